// round 16
// baseline (speedup 1.0000x reference)
#include <cuda_runtime.h>
#include <cuda_fp16.h>
#include <math.h>
#include <cstdint>

// Problem shape (fixed by the reference).
#define Bq      4
#define SEQ     2048
#define DMODEL  1024
#define NH      16
#define DH      64
#define ROWS    (Bq * SEQ)      // 8192

#define F32_EPS 1.1920929e-07f

// fp16 scratch: device globals (no cudaMalloc allowed).
__device__ __half g_xh[ROWS * DMODEL];
__device__ __half g_Wqh[DMODEL * DMODEL];
__device__ __half g_Wkh[DMODEL * DMODEL];
__device__ __half g_Wvh[DMODEL * DMODEL];
__device__ __half g_Woh[DMODEL * DMODEL];
__device__ __half g_Qh[ROWS * DMODEL];
__device__ __half g_Kh[ROWS * DMODEL];
__device__ __half g_Vh[ROWS * DMODEL];
__device__ __half g_Oh[ROWS * DMODEL];

// ===========================================================================
// Helpers.
// ===========================================================================
__device__ __forceinline__ uint32_t smem_to_u32(const void* p) {
    uint32_t a;
    asm("{ .reg .u64 t; cvta.to.shared.u64 t, %1; cvt.u32.u64 %0, t; }"
        : "=r"(a) : "l"(p));
    return a;
}
__device__ __forceinline__ void mma_f16(float* c, uint32_t a0, uint32_t a1,
                                        uint32_t a2, uint32_t a3,
                                        uint32_t b0, uint32_t b1) {
    asm volatile(
        "mma.sync.aligned.m16n8k16.row.col.f32.f16.f16.f32 "
        "{%0,%1,%2,%3}, {%4,%5,%6,%7}, {%8,%9}, {%0,%1,%2,%3};"
        : "+f"(c[0]), "+f"(c[1]), "+f"(c[2]), "+f"(c[3])
        : "r"(a0), "r"(a1), "r"(a2), "r"(a3), "r"(b0), "r"(b1));
}
__device__ __forceinline__ void ldsm_x4(uint32_t& r0, uint32_t& r1,
                                        uint32_t& r2, uint32_t& r3, uint32_t a) {
    asm volatile("ldmatrix.sync.aligned.m8n8.x4.shared.b16 {%0,%1,%2,%3}, [%4];"
                 : "=r"(r0), "=r"(r1), "=r"(r2), "=r"(r3) : "r"(a));
}
__device__ __forceinline__ void ldsm_x4_t(uint32_t& r0, uint32_t& r1,
                                          uint32_t& r2, uint32_t& r3, uint32_t a) {
    asm volatile("ldmatrix.sync.aligned.m8n8.x4.trans.shared.b16 {%0,%1,%2,%3}, [%4];"
                 : "=r"(r0), "=r"(r1), "=r"(r2), "=r"(r3) : "r"(a));
}
__device__ __forceinline__ void cp_async16(uint32_t dst, const void* src) {
    asm volatile("cp.async.cg.shared.global [%0], [%1], 16;"
                 :: "r"(dst), "l"(src));
}
#define CP_COMMIT() asm volatile("cp.async.commit_group;" ::: "memory")
#define CP_WAIT(n)  asm volatile("cp.async.wait_group %0;" :: "n"(n) : "memory")

#define MBARRIER_INIT(mbar, count) \
    asm volatile("mbarrier.init.shared.b64 [%0], %1;" \
        :: "r"((uint32_t)(mbar)), "r"((uint32_t)(count)) : "memory")
#define MBARRIER_ARRIVE(mbar) \
    asm volatile("mbarrier.arrive.shared.b64 _, [%0];" \
        :: "r"((uint32_t)(mbar)) : "memory")
// .noinc is LOAD-BEARING: without it the arrive-on increments the expected
// count at issue and consumes its own increment (net zero) => deadlock.
#define CP_ASYNC_MBARRIER_ARRIVE_NOINC(mbar) \
    asm volatile("cp.async.mbarrier.arrive.noinc.shared.b64 [%0];" \
        :: "r"((uint32_t)(mbar)) : "memory")
#define MBARRIER_WAIT_PARITY(mbar_smem_addr, phase_parity) do { \
    uint32_t _mbar = (uint32_t)(mbar_smem_addr); \
    uint32_t _parity = (uint32_t)(phase_parity); \
    uint32_t _done; \
    asm volatile("{\n\t.reg .pred p;\n\t" \
        "mbarrier.try_wait.parity.acquire.cta.shared::cta.b64 p, [%1], %2;\n\t" \
        "selp.b32 %0, 1, 0, p;\n\t}" \
        : "=r"(_done) : "r"(_mbar), "r"(_parity) : "memory"); \
    if (!_done) { \
        asm volatile("{\n\t.reg .pred P1;\n\t" \
            "WAIT_LOOP_%=:\n\t" \
            "mbarrier.try_wait.parity.acquire.cta.shared::cta.b64 P1, [%0], %1, 0x989680;\n\t" \
            "@P1 bra.uni WAIT_DONE_%=;\n\t" \
            "bra.uni WAIT_LOOP_%=;\n\t" \
            "WAIT_DONE_%=:\n\t}" \
            :: "r"(_mbar), "r"(_parity) : "memory"); \
    } \
} while (0)

__device__ __forceinline__ uint32_t packh2(float x, float y) {
    __half2 h = __floats2half2_rn(x, y);
    return *(uint32_t*)&h;
}
__device__ __forceinline__ uint32_t h2ex2(uint32_t x) {
    uint32_t r;
    asm("ex2.approx.f16x2 %0, %1;" : "=r"(r) : "r"(x));
    return r;
}

// ===========================================================================
// fp32 -> fp16 conversion, MLP=4 (R12 config).
// ===========================================================================
#define NX4 (ROWS * DMODEL / 4)
#define NW4 (DMODEL * DMODEL / 4)
#define NTOT4 (NX4 + 4 * NW4)
#define CVT_TPB 256
#define CVT_PER_THREAD 4
#define CVT_BLOCKS (NTOT4 / (CVT_TPB * CVT_PER_THREAD))

__global__ void __launch_bounds__(CVT_TPB)
cvt_all(const float4* __restrict__ x,
        const float4* __restrict__ w0, const float4* __restrict__ w1,
        const float4* __restrict__ w2, const float4* __restrict__ w3,
        uint2* __restrict__ dx, uint2* __restrict__ dw0,
        uint2* __restrict__ dw1, uint2* __restrict__ dw2,
        uint2* __restrict__ dw3)
{
    const int base = blockIdx.x * (CVT_TPB * CVT_PER_THREAD);
    const float4* s;
    uint2* d;
    int rbase;
    if (base < NX4) {
        s = x; d = dx; rbase = base;
    } else {
        int j = base - NX4;
        int wsel = j >> 18;
        rbase = j & (NW4 - 1);
        s = wsel == 0 ? w0 : wsel == 1 ? w1 : wsel == 2 ? w2 : w3;
        d = wsel == 0 ? dw0 : wsel == 1 ? dw1 : wsel == 2 ? dw2 : dw3;
    }
    float4 v[CVT_PER_THREAD];
#pragma unroll
    for (int i = 0; i < CVT_PER_THREAD; i++)
        v[i] = s[rbase + threadIdx.x + i * CVT_TPB];
#pragma unroll
    for (int i = 0; i < CVT_PER_THREAD; i++)
        d[rbase + threadIdx.x + i * CVT_TPB] =
            make_uint2(packh2(v[i].x, v[i].y), packh2(v[i].z, v[i].w));
}

// ===========================================================================
// WARP-SPECIALIZED fp16 GEMM (R15 config, byte-identical).
// ===========================================================================
#define GBK     64
#define GNCH    (DMODEL / GBK)       // 16
#define GASTR   72
#define GMATB   (128 * GASTR * 2)    // 18432
#define GSTGB   (2 * GMATB)          // 36864
#define GMB_OFF (3 * GSTGB)          // 110592
#define GSM_BYTES (GMB_OFF + 64)     // 110656

__device__ __forceinline__ void
gemm_body(__half* gsm, const __half* __restrict__ A, const __half* __restrict__ B,
          void* __restrict__ Cv, const float* __restrict__ w,
          int do_rms, int out_half, int bm, int bn)
{
    const uint32_t sb = smem_to_u32(gsm);
    const uint32_t mb = sb + GMB_OFF;
    const int tid  = threadIdx.x;
    const int wid  = tid >> 5;
    const int lane = tid & 31;

    if (tid == 0) {
#pragma unroll
        for (int s = 0; s < 3; s++) {
            MBARRIER_INIT(mb + s * 16, 32);
            MBARRIER_INIT(mb + s * 16 + 8, 128);
        }
    }
    __syncthreads();

    if (wid == 4) {
        const __half* Ag = A + (size_t)bm * DMODEL;
        const __half* Bg = B + (size_t)bn * DMODEL;
        for (int i = 0; i < GNCH; i++) {
            const int s = i % 3;
            const int c = i / 3;
            if (c > 0) MBARRIER_WAIT_PARITY(mb + s * 16 + 8, (c - 1) & 1);
            const uint32_t abase = sb + (uint32_t)s * GSTGB;
            const uint32_t bbase = abase + GMATB;
            const int kofs = i * GBK;
#pragma unroll
            for (int j = 0; j < 32; j++) {
                const int slot = lane + j * 32;
                const int row = slot >> 3;
                const int c8  = slot & 7;
                const uint32_t so = (uint32_t)(row * GASTR + c8 * 8) * 2u;
                const size_t go = (size_t)row * DMODEL + kofs + c8 * 8;
                cp_async16(abase + so, Ag + go);
                cp_async16(bbase + so, Bg + go);
            }
            CP_ASYNC_MBARRIER_ARRIVE_NOINC(mb + s * 16);
        }
        return;
    }

    const int g    = lane >> 2;
    const int t    = lane & 3;
    const int warpM = wid >> 1;
    const int warpN = wid & 1;
    const int l15 = lane & 15, lq = lane >> 4;
    const int rbl = lq * 8 + (lane & 7);
    const int cob = ((lane >> 3) & 1) * 8;

    float acc[4][8][4];
#pragma unroll
    for (int i = 0; i < 4; i++)
#pragma unroll
        for (int j = 0; j < 8; j++)
#pragma unroll
            for (int k = 0; k < 4; k++) acc[i][j][k] = 0.f;

    for (int i = 0; i < GNCH; i++) {
        const int s = i % 3;
        const int c = i / 3;
        MBARRIER_WAIT_PARITY(mb + s * 16, c & 1);

        const uint32_t abase = sb + (uint32_t)s * GSTGB;
        const uint32_t bbase = abase + GMATB;
#pragma unroll
        for (int ks = 0; ks < 4; ks++) {
            uint32_t a[4][4];
#pragma unroll
            for (int mf = 0; mf < 4; mf++)
                ldsm_x4(a[mf][0], a[mf][1], a[mf][2], a[mf][3],
                        abase + (uint32_t)((warpM * 64 + mf * 16 + l15) * GASTR
                                           + ks * 16 + lq * 8) * 2u);
#pragma unroll
            for (int nfp = 0; nfp < 4; nfp++) {
                uint32_t b0, b1, b2, b3;
                ldsm_x4(b0, b1, b2, b3,
                        bbase + (uint32_t)((warpN * 64 + nfp * 16 + rbl) * GASTR
                                           + ks * 16 + cob) * 2u);
#pragma unroll
                for (int mf = 0; mf < 4; mf++) {
                    mma_f16(acc[mf][2 * nfp],     a[mf][0], a[mf][1], a[mf][2], a[mf][3], b0, b1);
                    mma_f16(acc[mf][2 * nfp + 1], a[mf][0], a[mf][1], a[mf][2], a[mf][3], b2, b3);
                }
            }
        }
        MBARRIER_ARRIVE(mb + s * 16 + 8);
    }

#pragma unroll
    for (int mf = 0; mf < 4; mf++) {
        if (do_rms) {
            float ssl = 0.f, ssh = 0.f;
#pragma unroll
            for (int nf = 0; nf < 8; nf++) {
                ssl += acc[mf][nf][0] * acc[mf][nf][0]
                     + acc[mf][nf][1] * acc[mf][nf][1];
                ssh += acc[mf][nf][2] * acc[mf][nf][2]
                     + acc[mf][nf][3] * acc[mf][nf][3];
            }
            ssl += __shfl_xor_sync(0xFFFFFFFFu, ssl, 1);
            ssl += __shfl_xor_sync(0xFFFFFFFFu, ssl, 2);
            ssh += __shfl_xor_sync(0xFFFFFFFFu, ssh, 1);
            ssh += __shfl_xor_sync(0xFFFFFFFFu, ssh, 2);
            const float rl = rsqrtf(ssl * (1.0f / 64.0f) + F32_EPS);
            const float rh = rsqrtf(ssh * (1.0f / 64.0f) + F32_EPS);
#pragma unroll
            for (int nf = 0; nf < 8; nf++) {
                const int hc = nf * 8 + 2 * t;
                const float w0 = w[hc], w1 = w[hc + 1];
                acc[mf][nf][0] *= rl * w0;
                acc[mf][nf][1] *= rl * w1;
                acc[mf][nf][2] *= rh * w0;
                acc[mf][nf][3] *= rh * w1;
            }
        }
        const int r0 = bm + warpM * 64 + mf * 16 + g;
        const int cc = bn + warpN * 64 + 2 * t;
        if (out_half) {
            __half* C = (__half*)Cv;
            uint32_t* c0 = (uint32_t*)(C + (size_t)r0 * DMODEL + cc);
            uint32_t* c1 = (uint32_t*)(C + (size_t)(r0 + 8) * DMODEL + cc);
#pragma unroll
            for (int nf = 0; nf < 8; nf++) {
                c0[nf * 4] = packh2(acc[mf][nf][0], acc[mf][nf][1]);
                c1[nf * 4] = packh2(acc[mf][nf][2], acc[mf][nf][3]);
            }
        } else {
            float* C = (float*)Cv;
            float* c0 = C + (size_t)r0 * DMODEL + cc;
            float* c1 = C + (size_t)(r0 + 8) * DMODEL + cc;
#pragma unroll
            for (int nf = 0; nf < 8; nf++) {
                *(float2*)(c0 + nf * 8) = make_float2(acc[mf][nf][0], acc[mf][nf][1]);
                *(float2*)(c1 + nf * 8) = make_float2(acc[mf][nf][2], acc[mf][nf][3]);
            }
        }
    }
}

__global__ void __launch_bounds__(160, 2)
gemm_qkv(const __half* __restrict__ A,
         const __half* __restrict__ Bqm, const __half* __restrict__ Bkm,
         const __half* __restrict__ Bvm,
         __half* __restrict__ Cq, __half* __restrict__ Ck, __half* __restrict__ Cv_,
         const float* __restrict__ qn, const float* __restrict__ kn)
{
    extern __shared__ __half gsm[];
    const int m = blockIdx.x >> 3;
    const int bn = (blockIdx.x & 7) * 128;
    const __half* B = m == 0 ? Bqm : m == 1 ? Bkm : Bvm;
    __half* C = m == 0 ? Cq : m == 1 ? Ck : Cv_;
    const float* w = m == 0 ? qn : m == 1 ? kn : nullptr;
    gemm_body(gsm, A, B, C, w, m < 2 ? 1 : 0, 1, blockIdx.y * 128, bn);
}

__global__ void __launch_bounds__(160, 2)
gemm_f16(const __half* __restrict__ A, const __half* __restrict__ B,
         void* __restrict__ Cv, const float* __restrict__ w,
         int do_rms, int out_half)
{
    extern __shared__ __half gsm[];
    gemm_body(gsm, A, B, Cv, w, do_rms, out_half,
              blockIdx.y * 128, blockIdx.x * 128);
}

// ===========================================================================
// WARP-SPECIALIZED fp16 flash attention: 160 threads.
//   warps 0-3: consumers (32 q-rows each; per-warp math identical to R13).
//   warp 4:    producer — all KV cp.async via 6-deep single-tile mbarrier ring.
// NO __syncthreads / wait_group in the mainloop.
// Slot t (0..5): K at t*FA_TILEH halves, V at (6+t)*FA_TILEH halves.
// ===========================================================================
#define HSTR 72
#define FA_TILEH (64 * HSTR)            // 4608 halves
#define FA_NT (SEQ / 64)                // 32 tiles
#define FA_NS 6                         // ring depth
#define FA_MB_OFF (12 * FA_TILEH * 2)   // 110592
#define FA_BYTES (FA_MB_OFF + 96)       // 110688

__global__ void __launch_bounds__(160, 2)
flash_attn_f16(const __half* __restrict__ Q, const __half* __restrict__ K,
               const __half* __restrict__ V, __half* __restrict__ O)
{
    extern __shared__ __half fs[];
    const uint32_t sb = smem_to_u32(fs);
    const uint32_t mb = sb + FA_MB_OFF;    // full[s]=mb+s*16, empty[s]=+8
    const int tid  = threadIdx.x;
    const int wid  = tid >> 5;
    const int lane = tid & 31;
    const int bh = blockIdx.y;
    const int b  = bh >> 4;
    const int h  = bh & 15;
    const size_t rowbase = (size_t)b * SEQ;
    const int qm0 = blockIdx.x * 128;

    if (tid == 0) {
#pragma unroll
        for (int s = 0; s < FA_NS; s++) {
            MBARRIER_INIT(mb + s * 16, 32);        // full: producer arrive-ons
            MBARRIER_INIT(mb + s * 16 + 8, 128);   // empty: consumer threads
        }
    }
    __syncthreads();

    // ---- stage Q (128 x 64 halves) into slot-0/1 region (consumers only) ----
    if (tid < 128) {
        const __half* Qg = Q + (rowbase + qm0) * DMODEL + h * DH;
#pragma unroll
        for (int i = 0; i < 8; i++) {
            const int idx = tid + i * 128;
            const int row = idx >> 3, c8 = idx & 7;
            cp_async16(sb + (uint32_t)(row * HSTR + c8 * 8) * 2u,
                       Qg + (size_t)row * DMODEL + c8 * 8);
        }
        CP_COMMIT(); CP_WAIT(0);
    }
    __syncthreads();

    uint32_t qf[2][4][4];
    if (tid < 128) {
        const int m0 = wid * 32;
        const int l15 = lane & 15, lq = lane >> 4;
        const __half2 qsc = __float2half2_rn(0.125f * 1.4426950408889634f);
#pragma unroll
        for (int mf = 0; mf < 2; mf++)
#pragma unroll
            for (int ks = 0; ks < 4; ks++) {
                ldsm_x4(qf[mf][ks][0], qf[mf][ks][1], qf[mf][ks][2], qf[mf][ks][3],
                        sb + (uint32_t)((m0 + mf * 16 + l15) * HSTR
                                        + ks * 16 + lq * 8) * 2u);
#pragma unroll
                for (int j = 0; j < 4; j++) {
                    __half2* hp = (__half2*)&qf[mf][ks][j];
                    *hp = __hmul2(*hp, qsc);
                }
            }
    }
    __syncthreads();   // Q region free; producer may start overwriting

    if (wid == 4) {
        // ---------------- producer: fill 6-deep KV ring ----------------
        for (int i = 0; i < FA_NT; i++) {
            const int s = i % FA_NS;
            const int c = i / FA_NS;
            if (c > 0) MBARRIER_WAIT_PARITY(mb + s * 16 + 8, (c - 1) & 1);
            const __half* Kg = K + (rowbase + i * 64) * DMODEL + h * DH;
            const __half* Vg = V + (rowbase + i * 64) * DMODEL + h * DH;
            const uint32_t kb = sb + (uint32_t)(s * FA_TILEH) * 2u;
            const uint32_t vb = sb + (uint32_t)((FA_NS + s) * FA_TILEH) * 2u;
#pragma unroll
            for (int j = 0; j < 16; j++) {
                const int slot = lane + j * 32;     // 0..511
                const int row = slot >> 3, c8 = slot & 7;
                const uint32_t so = (uint32_t)(row * HSTR + c8 * 8) * 2u;
                const size_t go = (size_t)row * DMODEL + c8 * 8;
                cp_async16(kb + so, Kg + go);
                cp_async16(vb + so, Vg + go);
            }
            CP_ASYNC_MBARRIER_ARRIVE_NOINC(mb + s * 16);
        }
        return;   // producer done
    }

    // ---------------- consumers (warps 0-3) ----------------
    const int g  = lane >> 2;
    const int t  = lane & 3;
    const int m0 = wid * 32;
    const int l15 = lane & 15, lq = lane >> 4;
    const int rbl = lq * 8 + (lane & 7);
    const int cob = ((lane >> 3) & 1) * 8;
    const int rv  = ((lane >> 3) & 1) * 8 + (lane & 7);
    const int cv  = lq * 8;
    (void)l15; (void)lq;

    float acc_o[2][8][4];
#pragma unroll
    for (int i = 0; i < 2; i++)
#pragma unroll
        for (int j = 0; j < 8; j++)
#pragma unroll
            for (int k = 0; k < 4; k++) acc_o[i][j][k] = 0.f;
    float lr[2][2] = {{0.f, 0.f}, {0.f, 0.f}};

    for (int it = 0; it < FA_NT; it++) {
        const int s = it % FA_NS;
        const int c = it / FA_NS;
        MBARRIER_WAIT_PARITY(mb + s * 16, c & 1);

        // ---- S = Q * K^T (log2 units) ----
        float sc[2][8][4];
#pragma unroll
        for (int i = 0; i < 2; i++)
#pragma unroll
            for (int j = 0; j < 8; j++)
#pragma unroll
                for (int k = 0; k < 4; k++) sc[i][j][k] = 0.f;

        const uint32_t kbase = sb + (uint32_t)(s * FA_TILEH) * 2u;
#pragma unroll
        for (int ks = 0; ks < 4; ks++) {
#pragma unroll
            for (int nfp = 0; nfp < 4; nfp++) {
                uint32_t b0, b1, b2, b3;
                ldsm_x4(b0, b1, b2, b3,
                        kbase + (uint32_t)((nfp * 16 + rbl) * HSTR
                                           + ks * 16 + cob) * 2u);
#pragma unroll
                for (int mf = 0; mf < 2; mf++) {
                    mma_f16(sc[mf][2 * nfp],     qf[mf][ks][0], qf[mf][ks][1],
                            qf[mf][ks][2], qf[mf][ks][3], b0, b1);
                    mma_f16(sc[mf][2 * nfp + 1], qf[mf][ks][0], qf[mf][ks][1],
                            qf[mf][ks][2], qf[mf][ks][3], b2, b3);
                }
            }
        }

        // ---- p = 2^s via f16x2 MUFU; half2 row sums; p IS the A-frag ----
        uint32_t ph[2][8][2];
#pragma unroll
        for (int mf = 0; mf < 2; mf++) {
            __half2 sum0 = __float2half2_rn(0.f);
            __half2 sum1 = __float2half2_rn(0.f);
#pragma unroll
            for (int nf = 0; nf < 8; nf++) {
                ph[mf][nf][0] = h2ex2(packh2(sc[mf][nf][0], sc[mf][nf][1]));
                ph[mf][nf][1] = h2ex2(packh2(sc[mf][nf][2], sc[mf][nf][3]));
                sum0 = __hadd2(sum0, *(__half2*)&ph[mf][nf][0]);
                sum1 = __hadd2(sum1, *(__half2*)&ph[mf][nf][1]);
            }
            float2 f0 = __half22float2(sum0);
            float2 f1 = __half22float2(sum1);
            lr[mf][0] += f0.x + f0.y;
            lr[mf][1] += f1.x + f1.y;
        }

        // ---- O += P * V ----
        const uint32_t vbase = sb + (uint32_t)((FA_NS + s) * FA_TILEH) * 2u;
#pragma unroll
        for (int ks = 0; ks < 4; ks++) {
#pragma unroll
            for (int nfp = 0; nfp < 4; nfp++) {
                uint32_t b0, b1, b2, b3;
                ldsm_x4_t(b0, b1, b2, b3,
                          vbase + (uint32_t)((ks * 16 + rv) * HSTR
                                             + nfp * 16 + cv) * 2u);
#pragma unroll
                for (int mf = 0; mf < 2; mf++) {
                    mma_f16(acc_o[mf][2 * nfp],
                            ph[mf][2 * ks][0], ph[mf][2 * ks][1],
                            ph[mf][2 * ks + 1][0], ph[mf][2 * ks + 1][1],
                            b0, b1);
                    mma_f16(acc_o[mf][2 * nfp + 1],
                            ph[mf][2 * ks][0], ph[mf][2 * ks][1],
                            ph[mf][2 * ks + 1][0], ph[mf][2 * ks + 1][1],
                            b2, b3);
                }
            }
        }
        MBARRIER_ARRIVE(mb + s * 16 + 8);
    }

    // ---- epilogue: reduce l across quad once, O / l -> fp16 global ----
#pragma unroll
    for (int mf = 0; mf < 2; mf++) {
        float l0 = lr[mf][0], l1 = lr[mf][1];
        l0 += __shfl_xor_sync(0xFFFFFFFFu, l0, 1);
        l0 += __shfl_xor_sync(0xFFFFFFFFu, l0, 2);
        l1 += __shfl_xor_sync(0xFFFFFFFFu, l1, 1);
        l1 += __shfl_xor_sync(0xFFFFFFFFu, l1, 2);
        const float inv0 = 1.f / l0;
        const float inv1 = 1.f / l1;
        __half* o0 = O + (rowbase + qm0 + m0 + mf * 16 + g) * (size_t)DMODEL
                       + h * DH + 2 * t;
        __half* o1 = o0 + 8 * DMODEL;
#pragma unroll
        for (int nf = 0; nf < 8; nf++) {
            *(uint32_t*)(o0 + nf * 8) =
                packh2(acc_o[mf][nf][0] * inv0, acc_o[mf][nf][1] * inv0);
            *(uint32_t*)(o1 + nf * 8) =
                packh2(acc_o[mf][nf][2] * inv1, acc_o[mf][nf][3] * inv1);
        }
    }
}

// ---------------------------------------------------------------------------
// Launch.
// ---------------------------------------------------------------------------
extern "C" void kernel_launch(void* const* d_in, const int* in_sizes, int n_in,
                              void* d_out, int out_size)
{
    const float* x  = (const float*)d_in[0];
    const float* Wq = (const float*)d_in[1];
    const float* Wk = (const float*)d_in[2];
    const float* Wv = (const float*)d_in[3];
    const float* Wo = (const float*)d_in[4];
    const float* qn = (const float*)d_in[5];
    const float* kn = (const float*)d_in[6];
    float* out = (float*)d_out;

    __half *xh, *wqh, *wkh, *wvh, *woh, *Qh, *Kh, *Vh, *Oh;
    cudaGetSymbolAddress((void**)&xh,  g_xh);
    cudaGetSymbolAddress((void**)&wqh, g_Wqh);
    cudaGetSymbolAddress((void**)&wkh, g_Wkh);
    cudaGetSymbolAddress((void**)&wvh, g_Wvh);
    cudaGetSymbolAddress((void**)&woh, g_Woh);
    cudaGetSymbolAddress((void**)&Qh,  g_Qh);
    cudaGetSymbolAddress((void**)&Kh,  g_Kh);
    cudaGetSymbolAddress((void**)&Vh,  g_Vh);
    cudaGetSymbolAddress((void**)&Oh,  g_Oh);

    cudaFuncSetAttribute(gemm_f16,
                         cudaFuncAttributeMaxDynamicSharedMemorySize, GSM_BYTES);
    cudaFuncSetAttribute(gemm_qkv,
                         cudaFuncAttributeMaxDynamicSharedMemorySize, GSM_BYTES);
    cudaFuncSetAttribute(flash_attn_f16,
                         cudaFuncAttributeMaxDynamicSharedMemorySize, FA_BYTES);

    cvt_all<<<CVT_BLOCKS, CVT_TPB>>>((const float4*)x, (const float4*)Wq,
                                     (const float4*)Wk, (const float4*)Wv,
                                     (const float4*)Wo,
                                     (uint2*)xh, (uint2*)wqh, (uint2*)wkh,
                                     (uint2*)wvh, (uint2*)woh);

    gemm_qkv<<<dim3(24, ROWS / 128), 160, GSM_BYTES>>>(
        xh, wqh, wkh, wvh, Qh, Kh, Vh, qn, kn);

    flash_attn_f16<<<dim3(SEQ / 128, Bq * NH), 160, FA_BYTES>>>(Qh, Kh, Vh, Oh);

    gemm_f16<<<dim3(DMODEL / 128, ROWS / 128), 160, GSM_BYTES>>>(
        Oh, woh, out, nullptr, 0, 0);
}

// round 17
// speedup vs baseline: 1.0046x; 1.0046x over previous
#include <cuda_runtime.h>
#include <cuda_fp16.h>
#include <math.h>
#include <cstdint>

// Problem shape (fixed by the reference).
#define Bq      4
#define SEQ     2048
#define DMODEL  1024
#define NH      16
#define DH      64
#define ROWS    (Bq * SEQ)      // 8192

#define F32_EPS 1.1920929e-07f

// fp16 scratch: device globals (no cudaMalloc allowed).
__device__ __half g_xh[ROWS * DMODEL];
__device__ __half g_Wqh[DMODEL * DMODEL];
__device__ __half g_Wkh[DMODEL * DMODEL];
__device__ __half g_Wvh[DMODEL * DMODEL];
__device__ __half g_Woh[DMODEL * DMODEL];
__device__ __half g_Qh[ROWS * DMODEL];
__device__ __half g_Kh[ROWS * DMODEL];
__device__ __half g_Vh[ROWS * DMODEL];
__device__ __half g_Oh[ROWS * DMODEL];

// ===========================================================================
// Helpers.
// ===========================================================================
__device__ __forceinline__ uint32_t smem_to_u32(const void* p) {
    uint32_t a;
    asm("{ .reg .u64 t; cvta.to.shared.u64 t, %1; cvt.u32.u64 %0, t; }"
        : "=r"(a) : "l"(p));
    return a;
}
__device__ __forceinline__ void mma_f16(float* c, uint32_t a0, uint32_t a1,
                                        uint32_t a2, uint32_t a3,
                                        uint32_t b0, uint32_t b1) {
    asm volatile(
        "mma.sync.aligned.m16n8k16.row.col.f32.f16.f16.f32 "
        "{%0,%1,%2,%3}, {%4,%5,%6,%7}, {%8,%9}, {%0,%1,%2,%3};"
        : "+f"(c[0]), "+f"(c[1]), "+f"(c[2]), "+f"(c[3])
        : "r"(a0), "r"(a1), "r"(a2), "r"(a3), "r"(b0), "r"(b1));
}
__device__ __forceinline__ void ldsm_x4(uint32_t& r0, uint32_t& r1,
                                        uint32_t& r2, uint32_t& r3, uint32_t a) {
    asm volatile("ldmatrix.sync.aligned.m8n8.x4.shared.b16 {%0,%1,%2,%3}, [%4];"
                 : "=r"(r0), "=r"(r1), "=r"(r2), "=r"(r3) : "r"(a));
}
__device__ __forceinline__ void ldsm_x4_t(uint32_t& r0, uint32_t& r1,
                                          uint32_t& r2, uint32_t& r3, uint32_t a) {
    asm volatile("ldmatrix.sync.aligned.m8n8.x4.trans.shared.b16 {%0,%1,%2,%3}, [%4];"
                 : "=r"(r0), "=r"(r1), "=r"(r2), "=r"(r3) : "r"(a));
}
__device__ __forceinline__ void cp_async16(uint32_t dst, const void* src) {
    asm volatile("cp.async.cg.shared.global [%0], [%1], 16;"
                 :: "r"(dst), "l"(src));
}
#define CP_COMMIT() asm volatile("cp.async.commit_group;" ::: "memory")
#define CP_WAIT(n)  asm volatile("cp.async.wait_group %0;" :: "n"(n) : "memory")

#define MBARRIER_INIT(mbar, count) \
    asm volatile("mbarrier.init.shared.b64 [%0], %1;" \
        :: "r"((uint32_t)(mbar)), "r"((uint32_t)(count)) : "memory")
#define MBARRIER_ARRIVE(mbar) \
    asm volatile("mbarrier.arrive.shared.b64 _, [%0];" \
        :: "r"((uint32_t)(mbar)) : "memory")
// .noinc is LOAD-BEARING: without it the arrive-on increments the expected
// count at issue and consumes its own increment (net zero) => deadlock.
#define CP_ASYNC_MBARRIER_ARRIVE_NOINC(mbar) \
    asm volatile("cp.async.mbarrier.arrive.noinc.shared.b64 [%0];" \
        :: "r"((uint32_t)(mbar)) : "memory")
#define MBARRIER_WAIT_PARITY(mbar_smem_addr, phase_parity) do { \
    uint32_t _mbar = (uint32_t)(mbar_smem_addr); \
    uint32_t _parity = (uint32_t)(phase_parity); \
    uint32_t _done; \
    asm volatile("{\n\t.reg .pred p;\n\t" \
        "mbarrier.try_wait.parity.acquire.cta.shared::cta.b64 p, [%1], %2;\n\t" \
        "selp.b32 %0, 1, 0, p;\n\t}" \
        : "=r"(_done) : "r"(_mbar), "r"(_parity) : "memory"); \
    if (!_done) { \
        asm volatile("{\n\t.reg .pred P1;\n\t" \
            "WAIT_LOOP_%=:\n\t" \
            "mbarrier.try_wait.parity.acquire.cta.shared::cta.b64 P1, [%0], %1, 0x989680;\n\t" \
            "@P1 bra.uni WAIT_DONE_%=;\n\t" \
            "bra.uni WAIT_LOOP_%=;\n\t" \
            "WAIT_DONE_%=:\n\t}" \
            :: "r"(_mbar), "r"(_parity) : "memory"); \
    } \
} while (0)

__device__ __forceinline__ uint32_t packh2(float x, float y) {
    __half2 h = __floats2half2_rn(x, y);
    return *(uint32_t*)&h;
}
__device__ __forceinline__ uint32_t h2ex2(uint32_t x) {
    uint32_t r;
    asm("ex2.approx.f16x2 %0, %1;" : "=r"(r) : "r"(x));
    return r;
}

// ===========================================================================
// fp32 -> fp16 conversion, MLP=4 (R12 config).
// ===========================================================================
#define NX4 (ROWS * DMODEL / 4)
#define NW4 (DMODEL * DMODEL / 4)
#define NTOT4 (NX4 + 4 * NW4)
#define CVT_TPB 256
#define CVT_PER_THREAD 4
#define CVT_BLOCKS (NTOT4 / (CVT_TPB * CVT_PER_THREAD))

__global__ void __launch_bounds__(CVT_TPB)
cvt_all(const float4* __restrict__ x,
        const float4* __restrict__ w0, const float4* __restrict__ w1,
        const float4* __restrict__ w2, const float4* __restrict__ w3,
        uint2* __restrict__ dx, uint2* __restrict__ dw0,
        uint2* __restrict__ dw1, uint2* __restrict__ dw2,
        uint2* __restrict__ dw3)
{
    const int base = blockIdx.x * (CVT_TPB * CVT_PER_THREAD);
    const float4* s;
    uint2* d;
    int rbase;
    if (base < NX4) {
        s = x; d = dx; rbase = base;
    } else {
        int j = base - NX4;
        int wsel = j >> 18;
        rbase = j & (NW4 - 1);
        s = wsel == 0 ? w0 : wsel == 1 ? w1 : wsel == 2 ? w2 : w3;
        d = wsel == 0 ? dw0 : wsel == 1 ? dw1 : wsel == 2 ? dw2 : dw3;
    }
    float4 v[CVT_PER_THREAD];
#pragma unroll
    for (int i = 0; i < CVT_PER_THREAD; i++)
        v[i] = s[rbase + threadIdx.x + i * CVT_TPB];
#pragma unroll
    for (int i = 0; i < CVT_PER_THREAD; i++)
        d[rbase + threadIdx.x + i * CVT_TPB] =
            make_uint2(packh2(v[i].x, v[i].y), packh2(v[i].z, v[i].w));
}

// ===========================================================================
// WARP-SPECIALIZED fp16 GEMM (R15 config, byte-identical).
// ===========================================================================
#define GBK     64
#define GNCH    (DMODEL / GBK)       // 16
#define GASTR   72
#define GMATB   (128 * GASTR * 2)    // 18432
#define GSTGB   (2 * GMATB)          // 36864
#define GMB_OFF (3 * GSTGB)          // 110592
#define GSM_BYTES (GMB_OFF + 64)     // 110656

__device__ __forceinline__ void
gemm_body(__half* gsm, const __half* __restrict__ A, const __half* __restrict__ B,
          void* __restrict__ Cv, const float* __restrict__ w,
          int do_rms, int out_half, int bm, int bn)
{
    const uint32_t sb = smem_to_u32(gsm);
    const uint32_t mb = sb + GMB_OFF;
    const int tid  = threadIdx.x;
    const int wid  = tid >> 5;
    const int lane = tid & 31;

    if (tid == 0) {
#pragma unroll
        for (int s = 0; s < 3; s++) {
            MBARRIER_INIT(mb + s * 16, 32);
            MBARRIER_INIT(mb + s * 16 + 8, 128);
        }
    }
    __syncthreads();

    if (wid == 4) {
        const __half* Ag = A + (size_t)bm * DMODEL;
        const __half* Bg = B + (size_t)bn * DMODEL;
        for (int i = 0; i < GNCH; i++) {
            const int s = i % 3;
            const int c = i / 3;
            if (c > 0) MBARRIER_WAIT_PARITY(mb + s * 16 + 8, (c - 1) & 1);
            const uint32_t abase = sb + (uint32_t)s * GSTGB;
            const uint32_t bbase = abase + GMATB;
            const int kofs = i * GBK;
#pragma unroll
            for (int j = 0; j < 32; j++) {
                const int slot = lane + j * 32;
                const int row = slot >> 3;
                const int c8  = slot & 7;
                const uint32_t so = (uint32_t)(row * GASTR + c8 * 8) * 2u;
                const size_t go = (size_t)row * DMODEL + kofs + c8 * 8;
                cp_async16(abase + so, Ag + go);
                cp_async16(bbase + so, Bg + go);
            }
            CP_ASYNC_MBARRIER_ARRIVE_NOINC(mb + s * 16);
        }
        return;
    }

    const int g    = lane >> 2;
    const int t    = lane & 3;
    const int warpM = wid >> 1;
    const int warpN = wid & 1;
    const int l15 = lane & 15, lq = lane >> 4;
    const int rbl = lq * 8 + (lane & 7);
    const int cob = ((lane >> 3) & 1) * 8;

    float acc[4][8][4];
#pragma unroll
    for (int i = 0; i < 4; i++)
#pragma unroll
        for (int j = 0; j < 8; j++)
#pragma unroll
            for (int k = 0; k < 4; k++) acc[i][j][k] = 0.f;

    for (int i = 0; i < GNCH; i++) {
        const int s = i % 3;
        const int c = i / 3;
        MBARRIER_WAIT_PARITY(mb + s * 16, c & 1);

        const uint32_t abase = sb + (uint32_t)s * GSTGB;
        const uint32_t bbase = abase + GMATB;
#pragma unroll
        for (int ks = 0; ks < 4; ks++) {
            uint32_t a[4][4];
#pragma unroll
            for (int mf = 0; mf < 4; mf++)
                ldsm_x4(a[mf][0], a[mf][1], a[mf][2], a[mf][3],
                        abase + (uint32_t)((warpM * 64 + mf * 16 + l15) * GASTR
                                           + ks * 16 + lq * 8) * 2u);
#pragma unroll
            for (int nfp = 0; nfp < 4; nfp++) {
                uint32_t b0, b1, b2, b3;
                ldsm_x4(b0, b1, b2, b3,
                        bbase + (uint32_t)((warpN * 64 + nfp * 16 + rbl) * GASTR
                                           + ks * 16 + cob) * 2u);
#pragma unroll
                for (int mf = 0; mf < 4; mf++) {
                    mma_f16(acc[mf][2 * nfp],     a[mf][0], a[mf][1], a[mf][2], a[mf][3], b0, b1);
                    mma_f16(acc[mf][2 * nfp + 1], a[mf][0], a[mf][1], a[mf][2], a[mf][3], b2, b3);
                }
            }
        }
        MBARRIER_ARRIVE(mb + s * 16 + 8);
    }

#pragma unroll
    for (int mf = 0; mf < 4; mf++) {
        if (do_rms) {
            float ssl = 0.f, ssh = 0.f;
#pragma unroll
            for (int nf = 0; nf < 8; nf++) {
                ssl += acc[mf][nf][0] * acc[mf][nf][0]
                     + acc[mf][nf][1] * acc[mf][nf][1];
                ssh += acc[mf][nf][2] * acc[mf][nf][2]
                     + acc[mf][nf][3] * acc[mf][nf][3];
            }
            ssl += __shfl_xor_sync(0xFFFFFFFFu, ssl, 1);
            ssl += __shfl_xor_sync(0xFFFFFFFFu, ssl, 2);
            ssh += __shfl_xor_sync(0xFFFFFFFFu, ssh, 1);
            ssh += __shfl_xor_sync(0xFFFFFFFFu, ssh, 2);
            const float rl = rsqrtf(ssl * (1.0f / 64.0f) + F32_EPS);
            const float rh = rsqrtf(ssh * (1.0f / 64.0f) + F32_EPS);
#pragma unroll
            for (int nf = 0; nf < 8; nf++) {
                const int hc = nf * 8 + 2 * t;
                const float w0 = w[hc], w1 = w[hc + 1];
                acc[mf][nf][0] *= rl * w0;
                acc[mf][nf][1] *= rl * w1;
                acc[mf][nf][2] *= rh * w0;
                acc[mf][nf][3] *= rh * w1;
            }
        }
        const int r0 = bm + warpM * 64 + mf * 16 + g;
        const int cc = bn + warpN * 64 + 2 * t;
        if (out_half) {
            __half* C = (__half*)Cv;
            uint32_t* c0 = (uint32_t*)(C + (size_t)r0 * DMODEL + cc);
            uint32_t* c1 = (uint32_t*)(C + (size_t)(r0 + 8) * DMODEL + cc);
#pragma unroll
            for (int nf = 0; nf < 8; nf++) {
                c0[nf * 4] = packh2(acc[mf][nf][0], acc[mf][nf][1]);
                c1[nf * 4] = packh2(acc[mf][nf][2], acc[mf][nf][3]);
            }
        } else {
            float* C = (float*)Cv;
            float* c0 = C + (size_t)r0 * DMODEL + cc;
            float* c1 = C + (size_t)(r0 + 8) * DMODEL + cc;
#pragma unroll
            for (int nf = 0; nf < 8; nf++) {
                *(float2*)(c0 + nf * 8) = make_float2(acc[mf][nf][0], acc[mf][nf][1]);
                *(float2*)(c1 + nf * 8) = make_float2(acc[mf][nf][2], acc[mf][nf][3]);
            }
        }
    }
}

__global__ void __launch_bounds__(160, 2)
gemm_qkv(const __half* __restrict__ A,
         const __half* __restrict__ Bqm, const __half* __restrict__ Bkm,
         const __half* __restrict__ Bvm,
         __half* __restrict__ Cq, __half* __restrict__ Ck, __half* __restrict__ Cv_,
         const float* __restrict__ qn, const float* __restrict__ kn)
{
    extern __shared__ __half gsm[];
    const int m = blockIdx.x >> 3;
    const int bn = (blockIdx.x & 7) * 128;
    const __half* B = m == 0 ? Bqm : m == 1 ? Bkm : Bvm;
    __half* C = m == 0 ? Cq : m == 1 ? Ck : Cv_;
    const float* w = m == 0 ? qn : m == 1 ? kn : nullptr;
    gemm_body(gsm, A, B, C, w, m < 2 ? 1 : 0, 1, blockIdx.y * 128, bn);
}

__global__ void __launch_bounds__(160, 2)
gemm_f16(const __half* __restrict__ A, const __half* __restrict__ B,
         void* __restrict__ Cv, const float* __restrict__ w,
         int do_rms, int out_half)
{
    extern __shared__ __half gsm[];
    gemm_body(gsm, A, B, Cv, w, do_rms, out_half,
              blockIdx.y * 128, blockIdx.x * 128);
}

// ===========================================================================
// fp16 flash attention — R13 shell (pair-granular KV ring, 128 threads,
// 2 CTAs/SM) with INTERLEAVED S/ex2: the S-MMAs for key-group nfp are
// immediately followed by that group's exponentials, so MUFU work overlaps
// the next group's tensor work instead of forming a serial wall.
// Accumulation orders (s over ks; l over nf; PV over ks) unchanged => same
// bit-exact result as R13/R15.
// ===========================================================================
#define HSTR 72
#define FA_TILEH (64 * HSTR)
#define FA_NT (SEQ / 64)
#define FA_NP (FA_NT / 2)
#define FA_BYTES (12 * FA_TILEH * 2)   // 110592

__global__ void __launch_bounds__(128, 2)
flash_attn_f16(const __half* __restrict__ Q, const __half* __restrict__ K,
               const __half* __restrict__ V, __half* __restrict__ O)
{
    extern __shared__ __half fs[];
    const uint32_t sb = smem_to_u32(fs);
    const int tid  = threadIdx.x;
    const int wid  = tid >> 5;
    const int lane = tid & 31;
    const int g    = lane >> 2;
    const int t    = lane & 3;
    const int bh = blockIdx.y;
    const int b  = bh >> 4;
    const int h  = bh & 15;
    const size_t rowbase = (size_t)b * SEQ;
    const int qm0 = blockIdx.x * 128;
    const int m0  = wid * 32;

    const int l15 = lane & 15, lq = lane >> 4;
    const int rbl = lq * 8 + (lane & 7);
    const int cob = ((lane >> 3) & 1) * 8;
    const int rv  = ((lane >> 3) & 1) * 8 + (lane & 7);
    const int cv  = lq * 8;

    {
        const __half* Qg = Q + (rowbase + qm0) * DMODEL + h * DH;
#pragma unroll
        for (int i = 0; i < 8; i++) {
            const int idx = tid + i * 128;
            const int row = idx >> 3, c8 = idx & 7;
            cp_async16(sb + (uint32_t)(row * HSTR + c8 * 8) * 2u,
                       Qg + (size_t)row * DMODEL + c8 * 8);
        }
        CP_COMMIT(); CP_WAIT(0);
        __syncthreads();
    }
    uint32_t qf[2][4][4];
    const __half2 qsc = __float2half2_rn(0.125f * 1.4426950408889634f);
#pragma unroll
    for (int mf = 0; mf < 2; mf++)
#pragma unroll
        for (int ks = 0; ks < 4; ks++) {
            ldsm_x4(qf[mf][ks][0], qf[mf][ks][1], qf[mf][ks][2], qf[mf][ks][3],
                    sb + (uint32_t)((m0 + mf * 16 + l15) * HSTR
                                    + ks * 16 + lq * 8) * 2u);
#pragma unroll
            for (int j = 0; j < 4; j++) {
                __half2* hp = (__half2*)&qf[mf][ks][j];
                *hp = __hmul2(*hp, qsc);
            }
        }
    __syncthreads();

    float acc_o[2][8][4];
#pragma unroll
    for (int i = 0; i < 2; i++)
#pragma unroll
        for (int j = 0; j < 8; j++)
#pragma unroll
            for (int k = 0; k < 4; k++) acc_o[i][j][k] = 0.f;
    float lr[2][2] = {{0.f, 0.f}, {0.f, 0.f}};

    auto load_kv = [&](int tile, int tb) {
        const __half* Kg = K + (rowbase + tile * 64) * DMODEL + h * DH;
        const __half* Vg = V + (rowbase + tile * 64) * DMODEL + h * DH;
        const uint32_t kb = sb + (uint32_t)(tb * FA_TILEH) * 2u;
        const uint32_t vb = sb + (uint32_t)((6 + tb) * FA_TILEH) * 2u;
#pragma unroll
        for (int i = 0; i < 4; i++) {
            const int idx = tid + i * 128;
            const int row = idx >> 3, c8 = idx & 7;
            const uint32_t so = (uint32_t)(row * HSTR + c8 * 8) * 2u;
            const size_t go = (size_t)row * DMODEL + c8 * 8;
            cp_async16(kb + so, Kg + go);
            cp_async16(vb + so, Vg + go);
        }
    };
    auto load_pair = [&](int p, int bset) {
        load_kv(2 * p,     2 * bset);
        load_kv(2 * p + 1, 2 * bset + 1);
        CP_COMMIT();
    };

    load_pair(0, 0);
    load_pair(1, 1);

    for (int p = 0; p < FA_NP; p++) {
        const int bset = p % 3;
        if (p + 1 < FA_NP) { CP_WAIT(1); } else { CP_WAIT(0); }
        __syncthreads();
        if (p + 2 < FA_NP) load_pair(p + 2, (p + 2) % 3);

#pragma unroll
        for (int sub = 0; sub < 2; sub++) {
            const int tb = 2 * bset + sub;
            const uint32_t kbase = sb + (uint32_t)(tb * FA_TILEH) * 2u;

            // ---- interleaved S + ex2, key-group (nfp) major ----
            uint32_t ph[2][8][2];
            __half2 sm0[2], sm1[2];
#pragma unroll
            for (int mf = 0; mf < 2; mf++) {
                sm0[mf] = __float2half2_rn(0.f);
                sm1[mf] = __float2half2_rn(0.f);
            }
#pragma unroll
            for (int nfp = 0; nfp < 4; nfp++) {
                float s0[2][4], s1[2][4];
#pragma unroll
                for (int mf = 0; mf < 2; mf++)
#pragma unroll
                    for (int k = 0; k < 4; k++) { s0[mf][k] = 0.f; s1[mf][k] = 0.f; }
#pragma unroll
                for (int ks = 0; ks < 4; ks++) {
                    uint32_t b0, b1, b2, b3;
                    ldsm_x4(b0, b1, b2, b3,
                            kbase + (uint32_t)((nfp * 16 + rbl) * HSTR
                                               + ks * 16 + cob) * 2u);
#pragma unroll
                    for (int mf = 0; mf < 2; mf++) {
                        mma_f16(s0[mf], qf[mf][ks][0], qf[mf][ks][1],
                                qf[mf][ks][2], qf[mf][ks][3], b0, b1);
                        mma_f16(s1[mf], qf[mf][ks][0], qf[mf][ks][1],
                                qf[mf][ks][2], qf[mf][ks][3], b2, b3);
                    }
                }
                // ex2 of this key group (overlaps next group's MMAs)
#pragma unroll
                for (int mf = 0; mf < 2; mf++) {
                    ph[mf][2 * nfp][0]     = h2ex2(packh2(s0[mf][0], s0[mf][1]));
                    ph[mf][2 * nfp][1]     = h2ex2(packh2(s0[mf][2], s0[mf][3]));
                    ph[mf][2 * nfp + 1][0] = h2ex2(packh2(s1[mf][0], s1[mf][1]));
                    ph[mf][2 * nfp + 1][1] = h2ex2(packh2(s1[mf][2], s1[mf][3]));
                    sm0[mf] = __hadd2(sm0[mf], *(__half2*)&ph[mf][2 * nfp][0]);
                    sm1[mf] = __hadd2(sm1[mf], *(__half2*)&ph[mf][2 * nfp][1]);
                    sm0[mf] = __hadd2(sm0[mf], *(__half2*)&ph[mf][2 * nfp + 1][0]);
                    sm1[mf] = __hadd2(sm1[mf], *(__half2*)&ph[mf][2 * nfp + 1][1]);
                }
            }
#pragma unroll
            for (int mf = 0; mf < 2; mf++) {
                float2 f0 = __half22float2(sm0[mf]);
                float2 f1 = __half22float2(sm1[mf]);
                lr[mf][0] += f0.x + f0.y;
                lr[mf][1] += f1.x + f1.y;
            }

            // ---- O += P * V (unchanged) ----
            const uint32_t vbase = sb + (uint32_t)((6 + tb) * FA_TILEH) * 2u;
#pragma unroll
            for (int ks = 0; ks < 4; ks++) {
#pragma unroll
                for (int nfp = 0; nfp < 4; nfp++) {
                    uint32_t b0, b1, b2, b3;
                    ldsm_x4_t(b0, b1, b2, b3,
                              vbase + (uint32_t)((ks * 16 + rv) * HSTR
                                                 + nfp * 16 + cv) * 2u);
#pragma unroll
                    for (int mf = 0; mf < 2; mf++) {
                        mma_f16(acc_o[mf][2 * nfp],
                                ph[mf][2 * ks][0], ph[mf][2 * ks][1],
                                ph[mf][2 * ks + 1][0], ph[mf][2 * ks + 1][1],
                                b0, b1);
                        mma_f16(acc_o[mf][2 * nfp + 1],
                                ph[mf][2 * ks][0], ph[mf][2 * ks][1],
                                ph[mf][2 * ks + 1][0], ph[mf][2 * ks + 1][1],
                                b2, b3);
                    }
                }
            }
        }
    }

#pragma unroll
    for (int mf = 0; mf < 2; mf++) {
        float l0 = lr[mf][0], l1 = lr[mf][1];
        l0 += __shfl_xor_sync(0xFFFFFFFFu, l0, 1);
        l0 += __shfl_xor_sync(0xFFFFFFFFu, l0, 2);
        l1 += __shfl_xor_sync(0xFFFFFFFFu, l1, 1);
        l1 += __shfl_xor_sync(0xFFFFFFFFu, l1, 2);
        const float inv0 = 1.f / l0;
        const float inv1 = 1.f / l1;
        __half* o0 = O + (rowbase + qm0 + m0 + mf * 16 + g) * (size_t)DMODEL
                       + h * DH + 2 * t;
        __half* o1 = o0 + 8 * DMODEL;
#pragma unroll
        for (int nf = 0; nf < 8; nf++) {
            *(uint32_t*)(o0 + nf * 8) =
                packh2(acc_o[mf][nf][0] * inv0, acc_o[mf][nf][1] * inv0);
            *(uint32_t*)(o1 + nf * 8) =
                packh2(acc_o[mf][nf][2] * inv1, acc_o[mf][nf][3] * inv1);
        }
    }
}

// ---------------------------------------------------------------------------
// Launch.
// ---------------------------------------------------------------------------
extern "C" void kernel_launch(void* const* d_in, const int* in_sizes, int n_in,
                              void* d_out, int out_size)
{
    const float* x  = (const float*)d_in[0];
    const float* Wq = (const float*)d_in[1];
    const float* Wk = (const float*)d_in[2];
    const float* Wv = (const float*)d_in[3];
    const float* Wo = (const float*)d_in[4];
    const float* qn = (const float*)d_in[5];
    const float* kn = (const float*)d_in[6];
    float* out = (float*)d_out;

    __half *xh, *wqh, *wkh, *wvh, *woh, *Qh, *Kh, *Vh, *Oh;
    cudaGetSymbolAddress((void**)&xh,  g_xh);
    cudaGetSymbolAddress((void**)&wqh, g_Wqh);
    cudaGetSymbolAddress((void**)&wkh, g_Wkh);
    cudaGetSymbolAddress((void**)&wvh, g_Wvh);
    cudaGetSymbolAddress((void**)&woh, g_Woh);
    cudaGetSymbolAddress((void**)&Qh,  g_Qh);
    cudaGetSymbolAddress((void**)&Kh,  g_Kh);
    cudaGetSymbolAddress((void**)&Vh,  g_Vh);
    cudaGetSymbolAddress((void**)&Oh,  g_Oh);

    cudaFuncSetAttribute(gemm_f16,
                         cudaFuncAttributeMaxDynamicSharedMemorySize, GSM_BYTES);
    cudaFuncSetAttribute(gemm_qkv,
                         cudaFuncAttributeMaxDynamicSharedMemorySize, GSM_BYTES);
    cudaFuncSetAttribute(flash_attn_f16,
                         cudaFuncAttributeMaxDynamicSharedMemorySize, FA_BYTES);

    cvt_all<<<CVT_BLOCKS, CVT_TPB>>>((const float4*)x, (const float4*)Wq,
                                     (const float4*)Wk, (const float4*)Wv,
                                     (const float4*)Wo,
                                     (uint2*)xh, (uint2*)wqh, (uint2*)wkh,
                                     (uint2*)wvh, (uint2*)woh);

    gemm_qkv<<<dim3(24, ROWS / 128), 160, GSM_BYTES>>>(
        xh, wqh, wkh, wvh, Qh, Kh, Vh, qn, kn);

    flash_attn_f16<<<dim3(SEQ / 128, Bq * NH), 128, FA_BYTES>>>(Qh, Kh, Vh, Oh);

    gemm_f16<<<dim3(DMODEL / 128, ROWS / 128), 160, GSM_BYTES>>>(
        Oh, woh, out, nullptr, 0, 0);
}